// round 2
// baseline (speedup 1.0000x reference)
#include <cuda_runtime.h>

#define BATCH   4
#define N1_PER  16384
#define N2_PER  4096
#define N1_TOT  (BATCH * N1_PER)
#define N2_TOT  (BATCH * N2_PER)
#define C_IN    512
#define C_OUT   256
#define BN_EPS  1e-5f

__device__ float g_h2[N2_TOT * C_OUT];
__device__ float g_W1s[C_OUT * C_OUT];
__device__ float g_W2s[C_IN * C_OUT];
__device__ float g_b1s[C_OUT];
__device__ float g_b2s[C_OUT];
__device__ float g_w3[N1_TOT * 3];
__device__ int   g_i3[N1_TOT * 3];

__global__ void prep_weights(const float* __restrict__ W1, const float* __restrict__ b1,
                             const float* __restrict__ g1, const float* __restrict__ be1,
                             const float* __restrict__ m1, const float* __restrict__ v1,
                             const float* __restrict__ W2, const float* __restrict__ b2,
                             const float* __restrict__ g2, const float* __restrict__ be2,
                             const float* __restrict__ m2, const float* __restrict__ v2)
{
    int n = blockIdx.x;
    float s1 = g1[n] * rsqrtf(v1[n] + BN_EPS);
    float s2 = g2[n] * rsqrtf(v2[n] + BN_EPS);
    for (int k = threadIdx.x; k < C_OUT; k += blockDim.x)
        g_W1s[k * C_OUT + n] = W1[n * C_OUT + k] * s1;
    for (int k = threadIdx.x; k < C_IN; k += blockDim.x)
        g_W2s[k * C_OUT + n] = W2[n * C_IN + k] * s2;
    if (threadIdx.x == 0) {
        g_b1s[n] = (b1[n] - m1[n]) * s1 + be1[n];
        g_b2s[n] = (b2[n] - m2[n]) * s2 + be2[n];
    }
}

template <int LAYER>
__global__ __launch_bounds__(256, 2)
void sgemm_bias_relu(const float* __restrict__ A, float* __restrict__ Cout,
                     int M, int K)
{
    const int N = C_OUT;
    const float* __restrict__ W    = (LAYER == 1) ? g_W1s : g_W2s;
    const float* __restrict__ bias = (LAYER == 1) ? g_b1s : g_b2s;
    float* __restrict__ C          = (LAYER == 1) ? Cout  : g_h2;

    __shared__ float As[8][128];
    __shared__ float Bs[8][128];

    const int tid = threadIdx.x;
    const int bx  = blockIdx.x;
    const int by  = blockIdx.y;
    const int tx  = tid & 15;
    const int ty  = tid >> 4;

    const int arow = tid >> 1;
    const int acol = (tid & 1) * 4;
    const int brow = tid >> 5;
    const int bcol = (tid & 31) * 4;

    const float* Abase = A + (size_t)(by * 128 + arow) * K + acol;
    const float* Wbase = W + (size_t)brow * N + bx * 128 + bcol;

    float acc[8][8];
#pragma unroll
    for (int i = 0; i < 8; i++)
#pragma unroll
        for (int j = 0; j < 8; j++) acc[i][j] = 0.f;

    for (int k0 = 0; k0 < K; k0 += 8) {
        float4 av = *(const float4*)(Abase + k0);
        float4 bv = *(const float4*)(Wbase + (size_t)k0 * N);
        __syncthreads();
        As[acol + 0][arow] = av.x;
        As[acol + 1][arow] = av.y;
        As[acol + 2][arow] = av.z;
        As[acol + 3][arow] = av.w;
        *(float4*)&Bs[brow][bcol] = bv;
        __syncthreads();

#pragma unroll
        for (int kk = 0; kk < 8; kk++) {
            float4 a0 = *(const float4*)&As[kk][ty * 4];
            float4 a1 = *(const float4*)&As[kk][64 + ty * 4];
            float4 b0 = *(const float4*)&Bs[kk][tx * 4];
            float4 b1 = *(const float4*)&Bs[kk][64 + tx * 4];
            float a[8] = {a0.x, a0.y, a0.z, a0.w, a1.x, a1.y, a1.z, a1.w};
            float b[8] = {b0.x, b0.y, b0.z, b0.w, b1.x, b1.y, b1.z, b1.w};
#pragma unroll
            for (int i = 0; i < 8; i++)
#pragma unroll
                for (int j = 0; j < 8; j++)
                    acc[i][j] = fmaf(a[i], b[j], acc[i][j]);
        }
    }

    const int col0 = bx * 128 + tx * 4;
    const int col1 = col0 + 64;
    float4 biasA = *(const float4*)&bias[col0];
    float4 biasB = *(const float4*)&bias[col1];

#pragma unroll
    for (int i = 0; i < 8; i++) {
        int row = by * 128 + ((i < 4) ? (ty * 4 + i) : (64 + ty * 4 + i - 4));
        float* Crow = C + (size_t)row * N;
        float4 v0, v1;
        v0.x = fmaxf(acc[i][0] + biasA.x, 0.f);
        v0.y = fmaxf(acc[i][1] + biasA.y, 0.f);
        v0.z = fmaxf(acc[i][2] + biasA.z, 0.f);
        v0.w = fmaxf(acc[i][3] + biasA.w, 0.f);
        v1.x = fmaxf(acc[i][4] + biasB.x, 0.f);
        v1.y = fmaxf(acc[i][5] + biasB.y, 0.f);
        v1.z = fmaxf(acc[i][6] + biasB.z, 0.f);
        v1.w = fmaxf(acc[i][7] + biasB.w, 0.f);
        *(float4*)&Crow[col0] = v0;
        *(float4*)&Crow[col1] = v1;
    }
}

__global__ __launch_bounds__(256)
void knn_search(const float* __restrict__ p1, const float* __restrict__ p2)
{
    __shared__ float sp[3 * N2_PER];

    const int b      = blockIdx.x >> 6;
    const int qblock = blockIdx.x & 63;
    const int tid    = threadIdx.x;

    const float* p2b = p2 + (size_t)b * N2_PER * 3;
    for (int t = tid; t < N2_PER * 3; t += 256) {
        float v  = p2b[t];
        int   pt = t / 3;
        int   c  = t - pt * 3;
        sp[c * N2_PER + pt] = v;
    }
    __syncthreads();

    const int q  = b * N1_PER + qblock * 256 + tid;
    const float qx = p1[q * 3 + 0];
    const float qy = p1[q * 3 + 1];
    const float qz = p1[q * 3 + 2];

    float d0 = 1e30f, d1 = 1e30f, d2b = 1e30f;
    int   i0 = 0,     i1 = 0,     i2 = 0;

#pragma unroll 8
    for (int j = 0; j < N2_PER; j++) {
        float dx = qx - sp[j];
        float dy = qy - sp[N2_PER + j];
        float dz = qz - sp[2 * N2_PER + j];
        float d2 = fmaf(dz, dz, fmaf(dy, dy, dx * dx));
        if (d2 < d2b) {
            if (d2 < d1) {
                d2b = d1; i2 = i1;
                if (d2 < d0) { d1 = d0; i1 = i0; d0 = d2; i0 = j; }
                else         { d1 = d2; i1 = j; }
            } else { d2b = d2; i2 = j; }
        }
    }

    float r0 = sqrtf(fmaxf(d0, 1e-12f));
    float r1 = sqrtf(fmaxf(d1, 1e-12f));
    float r2 = sqrtf(fmaxf(d2b, 1e-12f));
    float w0 = 1.f / (r0 + 1e-8f);
    float w1 = 1.f / (r1 + 1e-8f);
    float w2 = 1.f / (r2 + 1e-8f);
    float inv = 1.f / (w0 + w1 + w2);

    g_w3[q * 3 + 0] = w0 * inv;
    g_w3[q * 3 + 1] = w1 * inv;
    g_w3[q * 3 + 2] = w2 * inv;
    g_i3[q * 3 + 0] = b * N2_PER + i0;
    g_i3[q * 3 + 1] = b * N2_PER + i1;
    g_i3[q * 3 + 2] = b * N2_PER + i2;
}

__global__ __launch_bounds__(256)
void gather_add(float* __restrict__ out)
{
    const int gid = blockIdx.x * 256 + threadIdx.x;
    const int q   = gid >> 6;
    const int c4  = gid & 63;

    float w0 = g_w3[q * 3 + 0];
    float w1 = g_w3[q * 3 + 1];
    float w2 = g_w3[q * 3 + 2];
    int   r0 = g_i3[q * 3 + 0];
    int   r1 = g_i3[q * 3 + 1];
    int   r2 = g_i3[q * 3 + 2];

    float4 f0 = *(const float4*)(g_h2 + (size_t)r0 * C_OUT + c4 * 4);
    float4 f1 = *(const float4*)(g_h2 + (size_t)r1 * C_OUT + c4 * 4);
    float4 f2 = *(const float4*)(g_h2 + (size_t)r2 * C_OUT + c4 * 4);

    float4* op = (float4*)out + (size_t)q * 64 + c4;
    float4 o = *op;
    o.x += w0 * f0.x + w1 * f1.x + w2 * f2.x;
    o.y += w0 * f0.y + w1 * f1.y + w2 * f2.y;
    o.z += w0 * f0.z + w1 * f1.z + w2 * f2.z;
    o.w += w0 * f0.w + w1 * f1.w + w2 * f2.w;
    *op = o;
}

extern "C" void kernel_launch(void* const* d_in, const int* in_sizes, int n_in,
                              void* d_out, int out_size)
{
    const float* p1 = (const float*)d_in[0];
    const float* x1 = (const float*)d_in[1];
    const float* p2 = (const float*)d_in[2];
    const float* x2 = (const float*)d_in[3];

    prep_weights<<<C_OUT, 256>>>((const float*)d_in[4],  (const float*)d_in[5],
                                 (const float*)d_in[6],  (const float*)d_in[7],
                                 (const float*)d_in[8],  (const float*)d_in[9],
                                 (const float*)d_in[10], (const float*)d_in[11],
                                 (const float*)d_in[12], (const float*)d_in[13],
                                 (const float*)d_in[14], (const float*)d_in[15]);

    {   // h2 = relu(bn(x2 @ W2^T)) -> g_h2
        dim3 grid(C_OUT / 128, N2_TOT / 128);
        sgemm_bias_relu<2><<<grid, 256>>>(x2, nullptr, N2_TOT, C_IN);
    }
    {   // h1 = relu(bn(x1 @ W1^T)) -> d_out
        dim3 grid(C_OUT / 128, N1_TOT / 128);
        sgemm_bias_relu<1><<<grid, 256>>>(x1, (float*)d_out, N1_TOT, C_OUT);
    }
    knn_search<<<BATCH * (N1_PER / 256), 256>>>(p1, p2);
    gather_add<<<(N1_TOT * 64) / 256, 256>>>((float*)d_out);
}

// round 6
// speedup vs baseline: 1.1146x; 1.1146x over previous
#include <cuda_runtime.h>

#define BATCH   4
#define N1_PER  16384
#define N2_PER  4096
#define N1_TOT  (BATCH * N1_PER)
#define N2_TOT  (BATCH * N2_PER)
#define C_IN    512
#define C_OUT   256
#define BN_EPS  1e-5f
#define KTILE   2048   // support points staged per smem tile (2 tiles per batch)

typedef unsigned long long ull;

__device__ float g_h2[N2_TOT * C_OUT];
__device__ float g_W1s[C_OUT * C_OUT];
__device__ float g_W2s[C_IN * C_OUT];
__device__ float g_b1s[C_OUT];
__device__ float g_b2s[C_OUT];
__device__ float g_w3[N1_TOT * 3];
__device__ int   g_i3[N1_TOT * 3];

// ---------------------------------------------------------------------------
// BN folding into weights/bias (W stored K-major [K][N])
// ---------------------------------------------------------------------------
__global__ void prep_weights(const float* __restrict__ W1, const float* __restrict__ b1,
                             const float* __restrict__ g1, const float* __restrict__ be1,
                             const float* __restrict__ m1, const float* __restrict__ v1,
                             const float* __restrict__ W2, const float* __restrict__ b2,
                             const float* __restrict__ g2, const float* __restrict__ be2,
                             const float* __restrict__ m2, const float* __restrict__ v2)
{
    int n = blockIdx.x;
    float s1 = g1[n] * rsqrtf(v1[n] + BN_EPS);
    float s2 = g2[n] * rsqrtf(v2[n] + BN_EPS);
    for (int k = threadIdx.x; k < C_OUT; k += blockDim.x)
        g_W1s[k * C_OUT + n] = W1[n * C_OUT + k] * s1;
    for (int k = threadIdx.x; k < C_IN; k += blockDim.x)
        g_W2s[k * C_OUT + n] = W2[n * C_IN + k] * s2;
    if (threadIdx.x == 0) {
        g_b1s[n] = (b1[n] - m1[n]) * s1 + be1[n];
        g_b2s[n] = (b2[n] - m2[n]) * s2 + be2[n];
    }
}

// ---------------------------------------------------------------------------
// SGEMM  C = relu(A[M,K] @ W[K,N] + bias[N]); 128x128 tile, BK=8,
// double-buffered smem (one __syncthreads per K-step).
// ---------------------------------------------------------------------------
template <int LAYER>
__global__ __launch_bounds__(256, 2)
void sgemm_bias_relu(const float* __restrict__ A, float* __restrict__ Cout,
                     int M, int K)
{
    const int N = C_OUT;
    const float* __restrict__ W    = (LAYER == 1) ? g_W1s : g_W2s;
    const float* __restrict__ bias = (LAYER == 1) ? g_b1s : g_b2s;
    float* __restrict__ C          = (LAYER == 1) ? Cout  : g_h2;

    __shared__ float As[2][8][128];
    __shared__ float Bs[2][8][128];

    const int tid = threadIdx.x;
    const int bx  = blockIdx.x;
    const int by  = blockIdx.y;
    const int tx  = tid & 15;
    const int ty  = tid >> 4;

    const int arow = tid >> 1;
    const int acol = (tid & 1) * 4;
    const int brow = tid >> 5;
    const int bcol = (tid & 31) * 4;

    const float* Abase = A + (size_t)(by * 128 + arow) * K + acol;
    const float* Wbase = W + (size_t)brow * N + bx * 128 + bcol;

    float acc[8][8];
#pragma unroll
    for (int i = 0; i < 8; i++)
#pragma unroll
        for (int j = 0; j < 8; j++) acc[i][j] = 0.f;

    // prologue: stage k0 = 0
    {
        float4 av = *(const float4*)(Abase);
        float4 bv = *(const float4*)(Wbase);
        As[0][acol + 0][arow] = av.x;
        As[0][acol + 1][arow] = av.y;
        As[0][acol + 2][arow] = av.z;
        As[0][acol + 3][arow] = av.w;
        *(float4*)&Bs[0][brow][bcol] = bv;
    }
    __syncthreads();

    int buf = 0;
    for (int k0 = 8; k0 <= K; k0 += 8) {
        float4 av2, bv2;
        const bool more = (k0 < K);
        if (more) {
            av2 = *(const float4*)(Abase + k0);
            bv2 = *(const float4*)(Wbase + (size_t)k0 * N);
        }

#pragma unroll
        for (int kk = 0; kk < 8; kk++) {
            float4 a0 = *(const float4*)&As[buf][kk][ty * 4];
            float4 a1 = *(const float4*)&As[buf][kk][64 + ty * 4];
            float4 b0 = *(const float4*)&Bs[buf][kk][tx * 4];
            float4 b1 = *(const float4*)&Bs[buf][kk][64 + tx * 4];
            float a[8] = {a0.x, a0.y, a0.z, a0.w, a1.x, a1.y, a1.z, a1.w};
            float b[8] = {b0.x, b0.y, b0.z, b0.w, b1.x, b1.y, b1.z, b1.w};
#pragma unroll
            for (int i = 0; i < 8; i++)
#pragma unroll
                for (int j = 0; j < 8; j++)
                    acc[i][j] = fmaf(a[i], b[j], acc[i][j]);
        }

        if (more) {
            int nb = buf ^ 1;
            As[nb][acol + 0][arow] = av2.x;
            As[nb][acol + 1][arow] = av2.y;
            As[nb][acol + 2][arow] = av2.z;
            As[nb][acol + 3][arow] = av2.w;
            *(float4*)&Bs[nb][brow][bcol] = bv2;
        }
        __syncthreads();
        buf ^= 1;
    }

    const int col0 = bx * 128 + tx * 4;
    const int col1 = col0 + 64;
    float4 biasA = *(const float4*)&bias[col0];
    float4 biasB = *(const float4*)&bias[col1];

#pragma unroll
    for (int i = 0; i < 8; i++) {
        int row = by * 128 + ((i < 4) ? (ty * 4 + i) : (64 + ty * 4 + i - 4));
        float* Crow = C + (size_t)row * N;
        float4 v0, v1;
        v0.x = fmaxf(acc[i][0] + biasA.x, 0.f);
        v0.y = fmaxf(acc[i][1] + biasA.y, 0.f);
        v0.z = fmaxf(acc[i][2] + biasA.z, 0.f);
        v0.w = fmaxf(acc[i][3] + biasA.w, 0.f);
        v1.x = fmaxf(acc[i][4] + biasB.x, 0.f);
        v1.y = fmaxf(acc[i][5] + biasB.y, 0.f);
        v1.z = fmaxf(acc[i][6] + biasB.z, 0.f);
        v1.w = fmaxf(acc[i][7] + biasB.w, 0.f);
        *(float4*)&Crow[col0] = v0;
        *(float4*)&Crow[col1] = v1;
    }
}

// ---------------------------------------------------------------------------
// packed f32x2 helpers
// ---------------------------------------------------------------------------
__device__ __forceinline__ ull pack2(float lo, float hi) {
    ull r;
    asm("mov.b64 %0, {%1, %2};" : "=l"(r) : "f"(lo), "f"(hi));
    return r;
}
__device__ __forceinline__ void unpack2(ull v, float& lo, float& hi) {
    asm("mov.b64 {%0, %1}, %2;" : "=f"(lo), "=f"(hi) : "l"(v));
}
__device__ __forceinline__ ull fma2(ull a, ull b, ull c) {
    ull r;
    asm("fma.rn.f32x2 %0, %1, %2, %3;" : "=l"(r) : "l"(a), "l"(b), "l"(c));
    return r;
}

__device__ __forceinline__ void upd3(float d, int j,
                                     float& d0, float& d1, float& d2,
                                     int& i0, int& i1, int& i2)
{
    if (d < d1) {
        d2 = d1; i2 = i1;
        if (d < d0) { d1 = d0; i1 = i0; d0 = d; i0 = j; }
        else        { d1 = d;  i1 = j; }
    } else { d2 = d; i2 = j; }
}

// ---------------------------------------------------------------------------
// 3-NN search, packed-pair form.
// Ranking key: r = |s|^2 - 2 q.s  (== d^2 - |q|^2, same ordering).
// smem layout per pair j: sA[j]=(x0,x1,y0,y1)  sB[j]=(z0,z1,w0,w1), w=|s|^2.
// 128 threads/block = 128 queries; 512 blocks; 2 tiles of 2048 support pts.
// ---------------------------------------------------------------------------
__global__ __launch_bounds__(128)
void knn_search(const float* __restrict__ p1, const float* __restrict__ p2)
{
    __shared__ float4 sA[KTILE / 2];   // 16 KB
    __shared__ float4 sB[KTILE / 2];   // 16 KB

    const int b    = blockIdx.x >> 7;        // 128 blocks per batch
    const int qblk = blockIdx.x & 127;
    const int tid  = threadIdx.x;

    const int q  = b * N1_PER + qblk * 128 + tid;
    const float qx = p1[q * 3 + 0];
    const float qy = p1[q * 3 + 1];
    const float qz = p1[q * 3 + 2];
    const float qq = qx * qx + qy * qy + qz * qz;

    const ull qxv = pack2(-2.f * qx, -2.f * qx);
    const ull qyv = pack2(-2.f * qy, -2.f * qy);
    const ull qzv = pack2(-2.f * qz, -2.f * qz);

    float d0 = 1e30f, d1 = 1e30f, d2 = 1e30f;
    int   i0 = 0,     i1 = 0,     i2 = 0;

    for (int t = 0; t < N2_PER / KTILE; t++) {
        __syncthreads();   // protect smem reuse across tiles
        const float* src = p2 + ((size_t)b * N2_PER + t * KTILE) * 3;
        for (int pt = tid; pt < KTILE; pt += 128) {
            float x = src[pt * 3 + 0];
            float y = src[pt * 3 + 1];
            float z = src[pt * 3 + 2];
            float w = fmaf(z, z, fmaf(y, y, x * x));
            int j = pt >> 1, h = pt & 1;
            float* a  = (float*)&sA[j];
            float* bb = (float*)&sB[j];
            a[h]      = x;
            a[2 + h]  = y;
            bb[h]     = z;
            bb[2 + h] = w;
        }
        __syncthreads();

        const int base = t * KTILE;
#pragma unroll 4
        for (int j = 0; j < KTILE / 2; j++) {
            float4 a = sA[j];
            float4 v = sB[j];
            ull xs = pack2(a.x, a.y);
            ull ys = pack2(a.z, a.w);
            ull zs = pack2(v.x, v.y);
            ull ws = pack2(v.z, v.w);
            ull r = fma2(qzv, zs, ws);
            r = fma2(qyv, ys, r);
            r = fma2(qxv, xs, r);
            float r0, r1;
            unpack2(r, r0, r1);
            if (r0 < d2) upd3(r0, base + 2 * j,     d0, d1, d2, i0, i1, i2);
            if (r1 < d2) upd3(r1, base + 2 * j + 1, d0, d1, d2, i0, i1, i2);
        }
    }

    // reconstruct true distances: d^2 = r + |q|^2
    float s0 = sqrtf(fmaxf(d0 + qq, 1e-12f));
    float s1 = sqrtf(fmaxf(d1 + qq, 1e-12f));
    float s2 = sqrtf(fmaxf(d2 + qq, 1e-12f));
    float w0 = 1.f / (s0 + 1e-8f);
    float w1 = 1.f / (s1 + 1e-8f);
    float w2 = 1.f / (s2 + 1e-8f);
    float inv = 1.f / (w0 + w1 + w2);

    g_w3[q * 3 + 0] = w0 * inv;
    g_w3[q * 3 + 1] = w1 * inv;
    g_w3[q * 3 + 2] = w2 * inv;
    g_i3[q * 3 + 0] = b * N2_PER + i0;
    g_i3[q * 3 + 1] = b * N2_PER + i1;
    g_i3[q * 3 + 2] = b * N2_PER + i2;
}

// ---------------------------------------------------------------------------
// Gather + accumulate: out[q][:] += sum_k w_k * h2[idx_k][:]
// ---------------------------------------------------------------------------
__global__ __launch_bounds__(256)
void gather_add(float* __restrict__ out)
{
    const int gid = blockIdx.x * 256 + threadIdx.x;
    const int q   = gid >> 6;
    const int c4  = gid & 63;

    float w0 = g_w3[q * 3 + 0];
    float w1 = g_w3[q * 3 + 1];
    float w2 = g_w3[q * 3 + 2];
    int   r0 = g_i3[q * 3 + 0];
    int   r1 = g_i3[q * 3 + 1];
    int   r2 = g_i3[q * 3 + 2];

    float4 f0 = *(const float4*)(g_h2 + (size_t)r0 * C_OUT + c4 * 4);
    float4 f1 = *(const float4*)(g_h2 + (size_t)r1 * C_OUT + c4 * 4);
    float4 f2 = *(const float4*)(g_h2 + (size_t)r2 * C_OUT + c4 * 4);

    float4* op = (float4*)out + (size_t)q * 64 + c4;
    float4 o = *op;
    o.x += w0 * f0.x + w1 * f1.x + w2 * f2.x;
    o.y += w0 * f0.y + w1 * f1.y + w2 * f2.y;
    o.z += w0 * f0.z + w1 * f1.z + w2 * f2.z;
    o.w += w0 * f0.w + w1 * f1.w + w2 * f2.w;
    *op = o;
}

extern "C" void kernel_launch(void* const* d_in, const int* in_sizes, int n_in,
                              void* d_out, int out_size)
{
    const float* p1 = (const float*)d_in[0];
    const float* x1 = (const float*)d_in[1];
    const float* p2 = (const float*)d_in[2];
    const float* x2 = (const float*)d_in[3];

    prep_weights<<<C_OUT, 256>>>((const float*)d_in[4],  (const float*)d_in[5],
                                 (const float*)d_in[6],  (const float*)d_in[7],
                                 (const float*)d_in[8],  (const float*)d_in[9],
                                 (const float*)d_in[10], (const float*)d_in[11],
                                 (const float*)d_in[12], (const float*)d_in[13],
                                 (const float*)d_in[14], (const float*)d_in[15]);

    {   // h2 = relu(bn(x2 @ W2^T)) -> g_h2
        dim3 grid(C_OUT / 128, N2_TOT / 128);
        sgemm_bias_relu<2><<<grid, 256>>>(x2, nullptr, N2_TOT, C_IN);
    }
    {   // h1 = relu(bn(x1 @ W1^T)) -> d_out
        dim3 grid(C_OUT / 128, N1_TOT / 128);
        sgemm_bias_relu<1><<<grid, 256>>>(x1, (float*)d_out, N1_TOT, C_OUT);
    }
    knn_search<<<BATCH * (N1_PER / 128), 128>>>(p1, p2);
    gather_add<<<(N1_TOT * 64) / 256, 256>>>((float*)d_out);
}